// round 7
// baseline (speedup 1.0000x reference)
#include <cuda_runtime.h>
#include <cstdint>

#define BB 128
#define TT 4096
#define NN 32
#define FULL 0xffffffffu
#define KSEG 32                 // segments per chain
#define SEGLEN (TT / KSEG)      // 128
#define WARM 20                 // warm-up steps (Hilbert contraction burn-in)
#define WPB 8                   // warps per block in fb
#define NCHUNK 16
#define CHUNK (TT / NCHUNK)

// Scratch tapes for scaled forward/backward messages (scale cancels in ratios).
__device__ float g_a[(size_t)BB * TT * NN];
__device__ float g_b[(size_t)BB * TT * NN];
__device__ float g_partial[BB][NCHUNK];

// One matvec step: share v across the warp via smem ping-pong, then
// y_lane = sum_i v_i * E_pairs, using packed f32x2 FMAs (row read as float4).
// Returns renormalized dot (scaled by rcp of element 0), all lanes.
__device__ __forceinline__ float matvec_step(float v, float (*buf)[NN],
                                             int p, int lane,
                                             const unsigned long long* E2)
{
    buf[p][lane] = v;
    __syncwarp();
    const float* row = &buf[p][0];
    float r = __frcp_rn(row[0]);                      // renorm, off critical path
    const float4* row4 = reinterpret_cast<const float4*>(row);
    unsigned long long acc0 = 0ull, acc1 = 0ull, acc2 = 0ull, acc3 = 0ull;
    #pragma unroll
    for (int k = 0; k < 8; k += 2) {
        float4 w0 = row4[k + 0];
        float4 w1 = row4[k + 1];
        unsigned long long wv0, wv1, wv2, wv3;
        asm("mov.b64 %0, {%1, %2};" : "=l"(wv0) : "f"(w0.x), "f"(w0.y));
        asm("mov.b64 %0, {%1, %2};" : "=l"(wv1) : "f"(w0.z), "f"(w0.w));
        asm("mov.b64 %0, {%1, %2};" : "=l"(wv2) : "f"(w1.x), "f"(w1.y));
        asm("mov.b64 %0, {%1, %2};" : "=l"(wv3) : "f"(w1.z), "f"(w1.w));
        asm("fma.rn.f32x2 %0, %1, %2, %0;" : "+l"(acc0) : "l"(wv0), "l"(E2[2 * k + 0]));
        asm("fma.rn.f32x2 %0, %1, %2, %0;" : "+l"(acc1) : "l"(wv1), "l"(E2[2 * k + 1]));
        asm("fma.rn.f32x2 %0, %1, %2, %0;" : "+l"(acc2) : "l"(wv2), "l"(E2[2 * k + 2]));
        asm("fma.rn.f32x2 %0, %1, %2, %0;" : "+l"(acc3) : "l"(wv3), "l"(E2[2 * k + 3]));
    }
    asm("add.rn.f32x2 %0, %0, %1;" : "+l"(acc0) : "l"(acc1));
    asm("add.rn.f32x2 %0, %0, %1;" : "+l"(acc2) : "l"(acc3));
    asm("add.rn.f32x2 %0, %0, %1;" : "+l"(acc0) : "l"(acc2));
    float lo, hi;
    asm("mov.b64 {%0, %1}, %2;" : "=f"(lo), "=f"(hi) : "l"(acc0));
    return (lo + hi) * r;
}

// ---------------------------------------------------------------------------
// Kernel 1: segmented forward/backward recursions. 8 warps per block; the
// 8 warps of a block are 8 consecutive segments of the SAME (batch, dir), so
// a block's warps have near-identical work and free their slot together.
// Lane = state. Probability-domain recursion with per-step rescale (scale
// cancels in the marginal ratio -> no log/lse anywhere). Mid-chain segments
// start WARM steps early from a uniform positive vector; diag(P)*E^T is a
// positive map contracting direction error ~0.32x/step (Hilbert metric)
// => ~1e-10 after 20 steps. Boundary segments use the exact init.
// ---------------------------------------------------------------------------
__global__ void __launch_bounds__(32 * WPB)
fb_kernel(const float* __restrict__ pots,
          const int*   __restrict__ lengths,
          const float* __restrict__ trans)
{
    __shared__ float buf[WPB][2][NN];

    const int lane = threadIdx.x & 31;
    const int w    = threadIdx.x >> 5;
    const int bid  = blockIdx.x;               // [0, BB * 2 * KSEG/WPB) = [0,1024)
    const int b    = bid >> 3;
    const int sub  = bid & 7;
    const bool fwd = (sub & 1) == 0;
    const int seg  = (sub >> 1) * WPB + w;

    const int len = lengths[b];
    const int t0  = seg * SEGLEN;
    if (t0 >= len) return;                     // segment beyond this chain
    int t1 = t0 + SEGLEN; if (t1 > len) t1 = len;

    const float* pot = pots + (size_t)b * TT * NN;
    unsigned long long E2[16];                 // packed exp(trans) pairs
    float (*mybuf)[NN] = buf[w];

    if (fwd) {
        // pair k packs exp(trans[2k][lane]), exp(trans[2k+1][lane])
        #pragma unroll
        for (int k = 0; k < 16; k++) {
            float e0 = __expf(trans[(2 * k)     * NN + lane]);
            float e1 = __expf(trans[(2 * k + 1) * NN + lane]);
            asm("mov.b64 %0, {%1, %2};" : "=l"(E2[k]) : "f"(e0), "f"(e1));
        }

        float* A = g_a + (size_t)b * TT * NN;

        int tstart = t0 - WARM; if (tstart < 0) tstart = 0;
        float a;
        if (tstart == 0) {
            a = __expf(pot[lane]);
            if (t0 == 0) A[lane] = a;
        } else {
            a = 1.0f;
        }

        float pr = pot[(size_t)(tstart + 1) * NN + lane];
        int t = tstart + 1;

        // warm-up (no stores)
        for (; t < t0; ++t) {
            float P = __expf(pr);
            pr = pot[(size_t)(t + 1) * NN + lane];
            float s = matvec_step(a, mybuf, t & 1, lane, E2);
            a = s * P;
        }
        // main (stores)
        for (; t < t1; ++t) {
            float P = __expf(pr);
            int tn = t + 1; if (tn > TT - 1) tn = TT - 1;
            pr = pot[(size_t)tn * NN + lane];
            float s = matvec_step(a, mybuf, t & 1, lane, E2);
            a = s * P;
            __stcs(&A[(size_t)t * NN + lane], a);
        }
    } else {
        // pair k packs exp(trans[lane][2k]), exp(trans[lane][2k+1])
        #pragma unroll
        for (int k = 0; k < 16; k++) {
            float e0 = __expf(trans[lane * NN + 2 * k]);
            float e1 = __expf(trans[lane * NN + 2 * k + 1]);
            asm("mov.b64 %0, {%1, %2};" : "=l"(E2[k]) : "f"(e0), "f"(e1));
        }

        float* Bv = g_b + (size_t)b * TT * NN;

        int tstart = t1 - 1 + WARM; if (tstart > len - 1) tstart = len - 1;
        float bv = 1.0f;                       // exact at len-1
        if (tstart < t1) Bv[(size_t)tstart * NN + lane] = 1.0f;

        float pr = pot[(size_t)tstart * NN + lane];
        int t = tstart;

        // warm-up: produce b_{t-1} for t-1 >= t1 (no stores)
        for (; t > t1; --t) {
            float P = __expf(pr);
            pr = pot[(size_t)(t - 1) * NN + lane];
            float s = matvec_step(bv * P, mybuf, t & 1, lane, E2);
            bv = s;
        }
        // main: produce and store b_{t-1} for t-1 in [t0, t1)
        for (; t >= t0 + 1; --t) {
            float P = __expf(pr);
            int tn = t - 1; if (tn < 0) tn = 0;
            pr = pot[(size_t)tn * NN + lane];
            float s = matvec_step(bv * P, mybuf, t & 1, lane, E2);
            bv = s;
            __stcs(&Bv[(size_t)(t - 1) * NN + lane], bv);
        }
    }
}

// ---------------------------------------------------------------------------
// Kernel 2: combine partials. grid (BB, NCHUNK); block (b,c) handles
// t in [c*CHUNK, (c+1)*CHUNK) ∩ [0,len). Deterministic per-slot partials.
// p_t(y_t) = a_y b_y / sum_k a_k b_k (per-t scales cancel).
// ---------------------------------------------------------------------------
__global__ void __launch_bounds__(256)
combine_kernel(const int* __restrict__ y_true,
               const int* __restrict__ lengths)
{
    const int b   = blockIdx.x;
    const int c   = blockIdx.y;
    const int tid = threadIdx.x;
    const int len = lengths[b];

    const int t_lo = c * CHUNK;
    int t_hi = t_lo + CHUNK; if (t_hi > len) t_hi = len;

    const float* Ab = g_a + (size_t)b * TT * NN;
    const float* Bb = g_b + (size_t)b * TT * NN;
    const int*   Yb = y_true + (size_t)b * TT;

    float part = 0.f;
    for (int t = t_lo + tid; t < t_hi; t += 256) {
        const float4* A4 = reinterpret_cast<const float4*>(Ab + (size_t)t * NN);
        const float4* B4 = reinterpret_cast<const float4*>(Bb + (size_t)t * NN);
        int y = Yb[t];
        float s = 0.f;
        float py = 0.f;
        #pragma unroll
        for (int q = 0; q < 8; q++) {
            float4 av = __ldcs(&A4[q]);
            float4 bv = __ldcs(&B4[q]);
            s += av.x * bv.x + av.y * bv.y + av.z * bv.z + av.w * bv.w;
            if (q == (y >> 2)) {
                float ae = (y & 3) == 0 ? av.x : (y & 3) == 1 ? av.y : (y & 3) == 2 ? av.z : av.w;
                float be = (y & 3) == 0 ? bv.x : (y & 3) == 1 ? bv.y : (y & 3) == 2 ? bv.z : bv.w;
                py = ae * be;
            }
        }
        part += __fdividef(py, s);
    }

    #pragma unroll
    for (int off = 16; off > 0; off >>= 1)
        part += __shfl_down_sync(FULL, part, off);

    __shared__ float red[8];
    if ((tid & 31) == 0) red[tid >> 5] = part;
    __syncthreads();
    if (tid == 0) {
        float s = 0.f;
        #pragma unroll
        for (int w2 = 0; w2 < 8; w2++) s += red[w2];
        g_partial[b][c] = s;
    }
}

// ---------------------------------------------------------------------------
__global__ void finalize_kernel(const int* __restrict__ lengths,
                                float* __restrict__ out)
{
    const int b = threadIdx.x;
    if (b >= BB) return;
    float inter = 0.f;
    #pragma unroll
    for (int c = 0; c < NCHUNK; c++) inter += g_partial[b][c];
    float flen = (float)lengths[b];
    float dice = (2.0f * inter + 1.0f) / (2.0f * flen + 1.0f);
    out[b] = 1.0f - dice;
}

// ---------------------------------------------------------------------------
extern "C" void kernel_launch(void* const* d_in, const int* in_sizes, int n_in,
                              void* d_out, int out_size)
{
    const float* pots    = (const float*)d_in[0];   // [B,T,N] fp32
    const int*   y_true  = (const int*)  d_in[1];   // [B,T] int32
    const int*   lengths = (const int*)  d_in[2];   // [B] int32
    const float* trans   = (const float*)d_in[3];   // [N,N] fp32
    float* out = (float*)d_out;                     // [B] fp32

    fb_kernel<<<(2 * BB * KSEG) / WPB, 32 * WPB>>>(pots, lengths, trans);
    combine_kernel<<<dim3(BB, NCHUNK), 256>>>(y_true, lengths);
    finalize_kernel<<<1, 128>>>(lengths, out);
}

// round 8
// speedup vs baseline: 1.0196x; 1.0196x over previous
#include <cuda_runtime.h>
#include <cuda_bf16.h>
#include <cstdint>

#define BB 128
#define TT 4096
#define NN 32
#define FULL 0xffffffffu
#define KSEG 32                 // segments per chain
#define SEGLEN (TT / KSEG)      // 128
#define WARM 20                 // warm-up steps (Hilbert contraction burn-in)
#define WPB 8                   // warps per block in fb
#define NCHUNK 16
#define CHUNK (TT / NCHUNK)

// bf16 tapes for scaled forward/backward messages (scale cancels in ratios;
// bf16 quantization error averages out in the dice sums -> ~1e-4 output err).
__device__ __nv_bfloat16 g_a[(size_t)BB * TT * NN];
__device__ __nv_bfloat16 g_b[(size_t)BB * TT * NN];
__device__ float g_partial[BB][NCHUNK];

// Dual matvec step: two independent chains share the warp. Each chain's v is
// broadcast via smem, then y_lane = sum_i v_i * E_pairs with packed f32x2
// FMAs. Returns the two renormalized dots (scaled by rcp of element 0).
__device__ __forceinline__ float2 matvec_dual(float va, float vb,
                                              float (*bufp)[NN], int lane,
                                              const unsigned long long* E2)
{
    bufp[0][lane] = va;
    bufp[1][lane] = vb;
    __syncwarp();
    const float4* rowA = reinterpret_cast<const float4*>(&bufp[0][0]);
    const float4* rowB = reinterpret_cast<const float4*>(&bufp[1][0]);
    float ra = __frcp_rn(bufp[0][0]);
    float rb = __frcp_rn(bufp[1][0]);
    unsigned long long aA0 = 0, aA1 = 0, aA2 = 0, aA3 = 0;
    unsigned long long aB0 = 0, aB1 = 0, aB2 = 0, aB3 = 0;
    #pragma unroll
    for (int k = 0; k < 8; k += 2) {
        float4 wa0 = rowA[k], wa1 = rowA[k + 1];
        float4 wb0 = rowB[k], wb1 = rowB[k + 1];
        unsigned long long pa0, pa1, pa2, pa3, pb0, pb1, pb2, pb3;
        asm("mov.b64 %0, {%1, %2};" : "=l"(pa0) : "f"(wa0.x), "f"(wa0.y));
        asm("mov.b64 %0, {%1, %2};" : "=l"(pa1) : "f"(wa0.z), "f"(wa0.w));
        asm("mov.b64 %0, {%1, %2};" : "=l"(pa2) : "f"(wa1.x), "f"(wa1.y));
        asm("mov.b64 %0, {%1, %2};" : "=l"(pa3) : "f"(wa1.z), "f"(wa1.w));
        asm("mov.b64 %0, {%1, %2};" : "=l"(pb0) : "f"(wb0.x), "f"(wb0.y));
        asm("mov.b64 %0, {%1, %2};" : "=l"(pb1) : "f"(wb0.z), "f"(wb0.w));
        asm("mov.b64 %0, {%1, %2};" : "=l"(pb2) : "f"(wb1.x), "f"(wb1.y));
        asm("mov.b64 %0, {%1, %2};" : "=l"(pb3) : "f"(wb1.z), "f"(wb1.w));
        asm("fma.rn.f32x2 %0, %1, %2, %0;" : "+l"(aA0) : "l"(pa0), "l"(E2[2 * k + 0]));
        asm("fma.rn.f32x2 %0, %1, %2, %0;" : "+l"(aB0) : "l"(pb0), "l"(E2[2 * k + 0]));
        asm("fma.rn.f32x2 %0, %1, %2, %0;" : "+l"(aA1) : "l"(pa1), "l"(E2[2 * k + 1]));
        asm("fma.rn.f32x2 %0, %1, %2, %0;" : "+l"(aB1) : "l"(pb1), "l"(E2[2 * k + 1]));
        asm("fma.rn.f32x2 %0, %1, %2, %0;" : "+l"(aA2) : "l"(pa2), "l"(E2[2 * k + 2]));
        asm("fma.rn.f32x2 %0, %1, %2, %0;" : "+l"(aB2) : "l"(pb2), "l"(E2[2 * k + 2]));
        asm("fma.rn.f32x2 %0, %1, %2, %0;" : "+l"(aA3) : "l"(pa3), "l"(E2[2 * k + 3]));
        asm("fma.rn.f32x2 %0, %1, %2, %0;" : "+l"(aB3) : "l"(pb3), "l"(E2[2 * k + 3]));
    }
    asm("add.rn.f32x2 %0, %0, %1;" : "+l"(aA0) : "l"(aA1));
    asm("add.rn.f32x2 %0, %0, %1;" : "+l"(aA2) : "l"(aA3));
    asm("add.rn.f32x2 %0, %0, %1;" : "+l"(aA0) : "l"(aA2));
    asm("add.rn.f32x2 %0, %0, %1;" : "+l"(aB0) : "l"(aB1));
    asm("add.rn.f32x2 %0, %0, %1;" : "+l"(aB2) : "l"(aB3));
    asm("add.rn.f32x2 %0, %0, %1;" : "+l"(aB0) : "l"(aB2));
    float la, ha, lb, hb;
    asm("mov.b64 {%0, %1}, %2;" : "=f"(la), "=f"(ha) : "l"(aA0));
    asm("mov.b64 {%0, %1}, %2;" : "=f"(lb), "=f"(hb) : "l"(aB0));
    return make_float2((la + ha) * ra, (lb + hb) * rb);
}

// ---------------------------------------------------------------------------
// Kernel 1: segmented fwd/bwd recursions, TWO segments per warp (j and j+16
// of the same batch+direction: identical E matrix, independent dependency
// chains -> 2x issue density at the same occupancy). Lane = state.
// Probability-domain recursion, per-step rescale (scale cancels in marginal
// ratios). Mid-chain segments start WARM steps early from a uniform vector;
// diag(P)E^T contracts direction error ~0.32x/step (Hilbert metric).
// Ragged clipping handled by clamped loads + predicated stores.
// ---------------------------------------------------------------------------
__global__ void __launch_bounds__(32 * WPB)
fb_kernel(const float* __restrict__ pots,
          const int*   __restrict__ lengths,
          const float* __restrict__ trans)
{
    __shared__ float buf[WPB][2][2][NN];

    const int lane = threadIdx.x & 31;
    const int w    = threadIdx.x >> 5;
    const int gw   = blockIdx.x * WPB + w;     // [0, 4096)
    const int b    = gw >> 5;
    const int rem  = gw & 31;
    const bool fwd = rem < 16;
    const int ps   = rem & 15;
    const int segA = ps, segB = ps + 16;

    const int len = lengths[b];
    const float* pot = pots + (size_t)b * TT * NN;

    const int t0A = segA * SEGLEN;
    const int t0B = segB * SEGLEN;
    if (t0A >= len) return;                    // then t0B >= len too
    const int t1A = (t0A + SEGLEN < len) ? t0A + SEGLEN : len;
    const int t1B = (t0B < len) ? ((t0B + SEGLEN < len) ? t0B + SEGLEN : len) : 0;

    unsigned long long E2[16];

    if (fwd) {
        #pragma unroll
        for (int k = 0; k < 16; k++) {
            float e0 = __expf(trans[(2 * k)     * NN + lane]);
            float e1 = __expf(trans[(2 * k + 1) * NN + lane]);
            asm("mov.b64 %0, {%1, %2};" : "=l"(E2[k]) : "f"(e0), "f"(e1));
        }
        __nv_bfloat16* A = g_a + (size_t)b * TT * NN;

        int tsA = t0A - WARM; if (tsA < 0) tsA = 0;
        int tsB = t0B - WARM;                  // t0B >= 2048, never clamps
        float aA = (tsA == 0) ? __expf(pot[lane]) : 1.0f;
        float aB = 1.0f;
        if (t0A == 0) A[lane] = __float2bfloat16(aA);

        int stepsA = t1A - 1 - tsA; if (stepsA < 0) stepsA = 0;
        int stepsB = t1B - 1 - tsB; if (stepsB < 0) stepsB = 0;
        const int nsteps = stepsA > stepsB ? stepsA : stepsB;

        int ta = tsA + 1, tb = tsB + 1;
        float prA = pot[(size_t)(ta <= TT - 1 ? ta : TT - 1) * NN + lane];
        float prB = pot[(size_t)(tb <= TT - 1 ? tb : TT - 1) * NN + lane];

        for (int k = 0; k < nsteps; ++k) {
            float Pa = __expf(prA);
            float Pb = __expf(prB);
            int na = ta + 1; if (na > TT - 1) na = TT - 1;
            int nb = tb + 1; if (nb > TT - 1) nb = TT - 1;
            prA = pot[(size_t)na * NN + lane];
            prB = pot[(size_t)nb * NN + lane];
            float2 s = matvec_dual(aA, aB, buf[w][k & 1], lane, E2);
            aA = s.x * Pa;
            aB = s.y * Pb;
            if (ta >= t0A && ta < t1A) A[(size_t)ta * NN + lane] = __float2bfloat16(aA);
            if (tb >= t0B && tb < t1B) A[(size_t)tb * NN + lane] = __float2bfloat16(aB);
            ++ta; ++tb;
        }
    } else {
        #pragma unroll
        for (int k = 0; k < 16; k++) {
            float e0 = __expf(trans[lane * NN + 2 * k]);
            float e1 = __expf(trans[lane * NN + 2 * k + 1]);
            asm("mov.b64 %0, {%1, %2};" : "=l"(E2[k]) : "f"(e0), "f"(e1));
        }
        __nv_bfloat16* Bv = g_b + (size_t)b * TT * NN;

        int tsA = t1A - 1 + WARM; if (tsA > len - 1) tsA = len - 1;
        int tsB = t1B - 1 + WARM; if (tsB > len - 1) tsB = len - 1;
        if (tsB < 0) tsB = 0;                   // inactive chain B
        float bA = 1.0f, bB = 1.0f;
        if (tsA < t1A) Bv[(size_t)tsA * NN + lane] = __float2bfloat16(1.0f);
        if (t1B > 0 && tsB < t1B) Bv[(size_t)tsB * NN + lane] = __float2bfloat16(1.0f);

        int stepsA = tsA - t0A; if (stepsA < 0) stepsA = 0;
        int stepsB = tsB - t0B; if (stepsB < 0) stepsB = 0;
        const int nsteps = stepsA > stepsB ? stepsA : stepsB;

        int ta = tsA, tb = tsB;
        float prA = pot[(size_t)ta * NN + lane];
        float prB = pot[(size_t)tb * NN + lane];

        for (int k = 0; k < nsteps; ++k) {
            float Pa = __expf(prA);
            float Pb = __expf(prB);
            int na = ta - 1; if (na < 0) na = 0;
            int nb = tb - 1; if (nb < 0) nb = 0;
            prA = pot[(size_t)na * NN + lane];
            prB = pot[(size_t)nb * NN + lane];
            float2 s = matvec_dual(bA * Pa, bB * Pb, buf[w][k & 1], lane, E2);
            bA = s.x;
            bB = s.y;
            if (ta - 1 >= t0A && ta - 1 < t1A) Bv[(size_t)(ta - 1) * NN + lane] = __float2bfloat16(bA);
            if (tb - 1 >= t0B && tb - 1 < t1B) Bv[(size_t)(tb - 1) * NN + lane] = __float2bfloat16(bB);
            --ta; --tb;
        }
    }
}

// ---------------------------------------------------------------------------
// Kernel 2: combine partials over bf16 tapes. grid (BB, NCHUNK).
// p_t(y_t) = a_y b_y / sum_k a_k b_k (per-t scales cancel).
// ---------------------------------------------------------------------------
__device__ __forceinline__ float2 bf2f(unsigned int u) {
    __nv_bfloat162 h = *reinterpret_cast<__nv_bfloat162*>(&u);
    return __bfloat1622float2(h);
}

__global__ void __launch_bounds__(256)
combine_kernel(const int* __restrict__ y_true,
               const int* __restrict__ lengths)
{
    const int b   = blockIdx.x;
    const int c   = blockIdx.y;
    const int tid = threadIdx.x;
    const int len = lengths[b];

    const int t_lo = c * CHUNK;
    int t_hi = t_lo + CHUNK; if (t_hi > len) t_hi = len;

    const __nv_bfloat16* Ab = g_a + (size_t)b * TT * NN;
    const __nv_bfloat16* Bb = g_b + (size_t)b * TT * NN;
    const int* Yb = y_true + (size_t)b * TT;

    float part = 0.f;
    for (int t = t_lo + tid; t < t_hi; t += 256) {
        const uint4* A4 = reinterpret_cast<const uint4*>(Ab + (size_t)t * NN);
        const uint4* B4 = reinterpret_cast<const uint4*>(Bb + (size_t)t * NN);
        int y = Yb[t];
        float s = 0.f, py = 0.f;
        #pragma unroll
        for (int q = 0; q < 4; q++) {
            uint4 ua = __ldcs(&A4[q]);
            uint4 ub = __ldcs(&B4[q]);
            unsigned int aw[4] = {ua.x, ua.y, ua.z, ua.w};
            unsigned int bw[4] = {ub.x, ub.y, ub.z, ub.w};
            #pragma unroll
            for (int i = 0; i < 4; i++) {
                float2 fa = bf2f(aw[i]);
                float2 fb = bf2f(bw[i]);
                s = fmaf(fa.x, fb.x, s);
                s = fmaf(fa.y, fb.y, s);
                if ((y >> 1) == q * 4 + i)
                    py = (y & 1) ? fa.y * fb.y : fa.x * fb.x;
            }
        }
        part += __fdividef(py, s);
    }

    #pragma unroll
    for (int off = 16; off > 0; off >>= 1)
        part += __shfl_down_sync(FULL, part, off);

    __shared__ float red[8];
    if ((tid & 31) == 0) red[tid >> 5] = part;
    __syncthreads();
    if (tid == 0) {
        float s = 0.f;
        #pragma unroll
        for (int w2 = 0; w2 < 8; w2++) s += red[w2];
        g_partial[b][c] = s;
    }
}

// ---------------------------------------------------------------------------
__global__ void finalize_kernel(const int* __restrict__ lengths,
                                float* __restrict__ out)
{
    const int b = threadIdx.x;
    if (b >= BB) return;
    float inter = 0.f;
    #pragma unroll
    for (int c = 0; c < NCHUNK; c++) inter += g_partial[b][c];
    float flen = (float)lengths[b];
    float dice = (2.0f * inter + 1.0f) / (2.0f * flen + 1.0f);
    out[b] = 1.0f - dice;
}

// ---------------------------------------------------------------------------
extern "C" void kernel_launch(void* const* d_in, const int* in_sizes, int n_in,
                              void* d_out, int out_size)
{
    const float* pots    = (const float*)d_in[0];   // [B,T,N] fp32
    const int*   y_true  = (const int*)  d_in[1];   // [B,T] int32
    const int*   lengths = (const int*)  d_in[2];   // [B] int32
    const float* trans   = (const float*)d_in[3];   // [N,N] fp32
    float* out = (float*)d_out;                     // [B] fp32

    fb_kernel<<<(2 * BB * KSEG) / (2 * WPB), 32 * WPB>>>(pots, lengths, trans);
    combine_kernel<<<dim3(BB, NCHUNK), 256>>>(y_true, lengths);
    finalize_kernel<<<1, 128>>>(lengths, out);
}